// round 16
// baseline (speedup 1.0000x reference)
#include <cuda_runtime.h>
#include <cstdint>

// Problem constants
#define BB   4096
#define TT   50
#define OBS  64
#define ACTD 16
#define DIN  80      // OBS + ACT
#define HH   256
#define G4   1024    // 4*H
#define NL   5
#define OUTD 64
#define KTOT 336

// Kernel config
#define RPB  32            // batch rows per CTA
#define NCTA (BB / RPB)    // 128
#define NTH  512
#define NW   16            // warps
#define SASD 64            // duplicated A row stride: 32 rows x 2 copies
#define PAN  6             // panel depth (336 = 56*6)
#define NPAN 56
#define PFLT (PAN * 64)    // 384 floats per warp panel
#define NBUF 2

// Shared memory (floats)
#define OFF_A0 0
#define OFF_A1 (KTOT * SASD)            // 21504
#define OFF_SB (2 * KTOT * SASD)        // 43008
#define OFF_P  (OFF_SB + G4)            // 44032
#define SMEM_FLOATS (OFF_P + NW * NBUF * PFLT)   // 56320 floats = 225280 B

typedef unsigned long long ull;

// Repacked LSTM weights: W6[k][wid<16][cgl<8][g<4][c<2]  (same as R15)
__device__ float W6buf[KTOT * G4];

__device__ __forceinline__ float sigf(float x) {
    return __fdividef(1.0f, 1.0f + __expf(-x));
}
__device__ __forceinline__ void ffma2(ull &d, ull a, ull b) {
    asm("fma.rn.f32x2 %0, %1, %2, %0;" : "+l"(d) : "l"(a), "l"(b));
}
__device__ __forceinline__ ull pk2(float lo, float hi) {
    ull r; asm("mov.b64 %0, {%1, %2};" : "=l"(r) : "f"(lo), "f"(hi)); return r;
}
__device__ __forceinline__ void upk2(ull v, float &lo, float &hi) {
    asm("mov.b64 {%0, %1}, %2;" : "=f"(lo), "=f"(hi) : "l"(v));
}
__device__ __forceinline__ uint32_t smem_u32(const void* p) {
    uint32_t a;
    asm("{ .reg .u64 t; cvta.to.shared.u64 t, %1; cvt.u32.u64 %0, t; }"
        : "=r"(a) : "l"(p));
    return a;
}
__device__ __forceinline__ void cpa16(uint32_t s, const float* g) {
    asm volatile("cp.async.cg.shared.global [%0], [%1], 16;" :: "r"(s), "l"(g));
}
#define CP_COMMIT() asm volatile("cp.async.commit_group;" ::: "memory")
#define CP_WAIT(n)  asm volatile("cp.async.wait_group %0;" :: "n"(n) : "memory")

__device__ __forceinline__ float gatef(float zi, float zf, float zg, float zo,
                                       float &c)
{
    const float ig = sigf(zi);
    const float fg = sigf(zf);
    const float gg = zg * sigf(zg);       // silu
    const float og = sigf(zo);
    const float cn = fg * c + ig * gg;
    c = cn;
    return og * cn * sigf(cn);            // o * silu(c_new)
}

// ---------------- prepass: repack [Wi;Wh] into W6 layout (unchanged) -------
__global__ void repack_kernel(const float* __restrict__ Wi,
                              const float* __restrict__ Wh)
{
    const int i = blockIdx.x * blockDim.x + threadIdx.x;
    if (i >= KTOT * G4) return;
    const int k   = i >> 10;
    const int rem = i & 1023;
    const int wid = rem >> 6;          // 0..15
    const int r6  = rem & 63;
    const int cgl = r6 >> 3;           // 0..7
    const int g   = (r6 >> 1) & 3;
    const int c   = r6 & 1;
    const int col = (g << 8) + (((wid << 3) + cgl) << 1) + c;
    W6buf[i] = (k < DIN) ? Wi[(size_t)k * G4 + col]
                         : Wh[(size_t)(k - DIN) * G4 + col];
}

__global__ void __launch_bounds__(NTH, 1)
lstm_fwd_kernel(const float* __restrict__ traj, const float* __restrict__ act,
                const float* __restrict__ bh,   const float* __restrict__ mlpW,
                const float* __restrict__ mlpB, const float* __restrict__ Wout,
                const float* __restrict__ bout, float* __restrict__ out)
{
    extern __shared__ float sm[];
    float* sB = sm + OFF_SB;

    const int tid  = threadIdx.x;
    const int lane = tid & 31;
    const int wid  = tid >> 5;       // 0..15
    const int row0 = blockIdx.x * RPB;
    const int rgrp = tid & 3;        // 4 row groups x 8 rows
    const int cgrp = tid >> 2;       // 0..127 colpairs (all 256 hk)
    const int cgl  = cgrp & 7;       // colpair within warp
    const int r0   = rgrp << 3;      // 0, 8, 16, 24

    float* cA = sm + OFF_A0;         // duplicated A: [k][row*2] (a,a)
    float* nA = sm + OFF_A1;
    float* pwarp = sm + OFF_P + wid * (NBUF * PFLT);
    const uint32_t pwb = smem_u32(pwarp);
    const float* wsrc = W6buf + (wid << 6);     // + k*1024

    // per-lane prefetch offsets: 3 x 16B chunks per panel (384 floats/warp)
    uint32_t pdst[3];
    uint32_t psrc[3];
    #pragma unroll
    for (int j = 0; j < 3; ++j) {
        const int o  = lane + (j << 5);   // 0..95
        const int kk = o >> 4;            // 0..5 (k row within panel)
        const int ch = o & 15;            // 16B chunk within 64-float row
        pdst[j] = (uint32_t)(kk * 64 + ch * 4) * 4;
        psrc[j] = (uint32_t)(kk * G4 + ch * 4);
    }

    const int hk0 = cgrp << 1;       // thread's col pair

    // cell state: creg[c*8 + r]
    float creg[16];
    #pragma unroll
    for (int i = 0; i < 16; ++i) creg[i] = 0.0f;

    // init: zero h region of buf0 (dup), cache bh, load x(0) dup
    for (int i = tid; i < HH * SASD; i += NTH) cA[DIN * SASD + i] = 0.0f;
    for (int i = tid; i < G4; i += NTH) sB[i] = bh[i];
    for (int i = tid; i < DIN * RPB; i += NTH) {
        const int r = i & 31, k = i >> 5;
        const int row = row0 + r;
        float v;
        if (k < OBS) v = traj[((size_t)row * TT) * OBS + k];
        else         v = act [((size_t)row * TT) * ACTD + (k - OBS)];
        *(ull*)(cA + k * SASD + (r << 1)) = pk2(v, v);
    }
    __syncthreads();

    // hoisted per-t invariants ------------------------------------------
    ull bgate[4];
    #pragma unroll
    for (int g = 0; g < 4; ++g)
        bgate[g] = pk2(sB[(g << 8) + hk0], sB[(g << 8) + hk0 + 1]);

    const float* xptr[5];
    int xoff[5];
    #pragma unroll
    for (int it = 0; it < 5; ++it) {
        const int i = tid + it * NTH;
        const int r = i & 31, k = i >> 5;
        const int row = row0 + r;
        xoff[it] = k * SASD + (r << 1);
        if (it < 4) xptr[it] = traj + ((size_t)row * TT + 1) * OBS + k;
        else        xptr[it] = act  + ((size_t)row * TT + 1) * ACTD + (k - OBS);
    }

    // prime ring: panel 0 -> buf 0
    #pragma unroll
    for (int j = 0; j < 3; ++j) cpa16(pwb + pdst[j], wsrc + psrc[j]);
    CP_COMMIT();

    int cb = 0;         // consume buffer
    int fpan = 1;       // next panel to fetch (mod NPAN; stream periodic in t)

    // ============================ LSTM over time ============================
    for (int t = 0; t < TT; ++t) {
        // acc[g*8 + r], bias-initialized from hoisted packs
        ull acc[32];
        #pragma unroll
        for (int g = 0; g < 4; ++g) {
            #pragma unroll
            for (int r = 0; r < 8; ++r) acc[g * 8 + r] = bgate[g];
        }

        // prefetch x(t+1) into registers
        float xv[5];
        if (t + 1 < TT) {
            #pragma unroll
            for (int it = 0; it < 5; ++it) xv[it] = *xptr[it];
            #pragma unroll
            for (int it = 0; it < 4; ++it) xptr[it] += OBS;
            xptr[4] += ACTD;
        }

        for (int p = 0; p < NPAN; ++p) {
            // prefetch next panel into the other buffer (periodic stream)
            {
                const float* s = wsrc + (size_t)fpan * (PAN * G4);
                const uint32_t d = pwb + (uint32_t)(cb ^ 1) * (PFLT * 4);
                #pragma unroll
                for (int j = 0; j < 3; ++j) cpa16(d + pdst[j], s + psrc[j]);
                CP_COMMIT();
                if (++fpan == NPAN) fpan = 0;
            }
            CP_WAIT(1);          // current panel (buf cb) complete
            __syncwarp();

            const float* panel = pwarp + cb * PFLT + (cgl << 3);
            const float* aptr  = cA + (p * PAN) * SASD + (r0 << 1);
            #pragma unroll
            for (int kk = 0; kk < PAN; ++kk) {
                // A: 4 LDS.128, each yields two ready packed operands (no packs)
                const ulonglong2 A0 = *(const ulonglong2*)(aptr);
                const ulonglong2 A1 = *(const ulonglong2*)(aptr + 4);
                const ulonglong2 A2 = *(const ulonglong2*)(aptr + 8);
                const ulonglong2 A3 = *(const ulonglong2*)(aptr + 12);
                const float* pr = panel + kk * 64;
                const ulonglong2 w01 = *(const ulonglong2*)(pr);     // g0, g1
                const ulonglong2 w23 = *(const ulonglong2*)(pr + 4); // g2, g3
                ffma2(acc[ 0], w01.x, A0.x); ffma2(acc[ 1], w01.x, A0.y);
                ffma2(acc[ 2], w01.x, A1.x); ffma2(acc[ 3], w01.x, A1.y);
                ffma2(acc[ 4], w01.x, A2.x); ffma2(acc[ 5], w01.x, A2.y);
                ffma2(acc[ 6], w01.x, A3.x); ffma2(acc[ 7], w01.x, A3.y);
                ffma2(acc[ 8], w01.y, A0.x); ffma2(acc[ 9], w01.y, A0.y);
                ffma2(acc[10], w01.y, A1.x); ffma2(acc[11], w01.y, A1.y);
                ffma2(acc[12], w01.y, A2.x); ffma2(acc[13], w01.y, A2.y);
                ffma2(acc[14], w01.y, A3.x); ffma2(acc[15], w01.y, A3.y);
                ffma2(acc[16], w23.x, A0.x); ffma2(acc[17], w23.x, A0.y);
                ffma2(acc[18], w23.x, A1.x); ffma2(acc[19], w23.x, A1.y);
                ffma2(acc[20], w23.x, A2.x); ffma2(acc[21], w23.x, A2.y);
                ffma2(acc[22], w23.x, A3.x); ffma2(acc[23], w23.x, A3.y);
                ffma2(acc[24], w23.y, A0.x); ffma2(acc[25], w23.y, A0.y);
                ffma2(acc[26], w23.y, A1.x); ffma2(acc[27], w23.y, A1.y);
                ffma2(acc[28], w23.y, A2.x); ffma2(acc[29], w23.y, A2.y);
                ffma2(acc[30], w23.y, A3.x); ffma2(acc[31], w23.y, A3.y);
                aptr += SASD;
            }
            __syncwarp();        // all lanes done before buf reuse
            cb ^= 1;
        }

        // gate epilogue -> h_new dup into NEXT buffer (vectorized STS.128)
        #pragma unroll
        for (int r = 0; r < 8; r += 2) {
            float zi0, zi1, zf0, zf1, zg0, zg1, zo0, zo1;
            upk2(acc[ 0 + r], zi0, zi1);
            upk2(acc[ 8 + r], zf0, zf1);
            upk2(acc[16 + r], zg0, zg1);
            upk2(acc[24 + r], zo0, zo1);
            const float h0a = gatef(zi0, zf0, zg0, zo0, creg[r]);
            const float h1a = gatef(zi1, zf1, zg1, zo1, creg[8 + r]);
            upk2(acc[ 0 + r + 1], zi0, zi1);
            upk2(acc[ 8 + r + 1], zf0, zf1);
            upk2(acc[16 + r + 1], zg0, zg1);
            upk2(acc[24 + r + 1], zo0, zo1);
            const float h0b = gatef(zi0, zf0, zg0, zo0, creg[r + 1]);
            const float h1b = gatef(zi1, zf1, zg1, zo1, creg[8 + r + 1]);
            ulonglong2 s0, s1;
            s0.x = pk2(h0a, h0a); s0.y = pk2(h0b, h0b);
            s1.x = pk2(h1a, h1a); s1.y = pk2(h1b, h1b);
            *(ulonglong2*)(nA + (DIN + hk0)     * SASD + ((r0 + r) << 1)) = s0;
            *(ulonglong2*)(nA + (DIN + hk0 + 1) * SASD + ((r0 + r) << 1)) = s1;
        }

        // commit x(t+1) dup at hoisted offsets; single barrier; swap
        if (t + 1 < TT) {
            #pragma unroll
            for (int it = 0; it < 5; ++it)
                *(ull*)(nA + xoff[it]) = pk2(xv[it], xv[it]);
        }
        __syncthreads();
        float* tmp = cA; cA = nA; nA = tmp;
    }
    CP_WAIT(0);   // drain overhanging prefetch

    // ============================ MLP head ============================
    // Thread: 4 rows x 4 cols; A operands come pre-packed from dup layout.
    {
        const int rg2 = tid & 7;
        const int cg2 = tid >> 3;        // 0..63
        const int rr0 = rg2 << 2;

        for (int l = 0; l < NL; ++l) {
            const float* Wl = mlpW + (size_t)l * HH * HH + (cg2 << 2);
            const int c0 = cg2 << 2;

            ull acc[8];
            {
                const ull b01 = pk2(mlpB[l * HH + c0],     mlpB[l * HH + c0 + 1]);
                const ull b23 = pk2(mlpB[l * HH + c0 + 2], mlpB[l * HH + c0 + 3]);
                #pragma unroll
                for (int r = 0; r < 4; ++r) { acc[r] = b01; acc[4 + r] = b23; }
            }

            #pragma unroll 4
            for (int k = 0; k < HH; ++k) {
                const float* ap = cA + (DIN + k) * SASD + (rr0 << 1);
                const ulonglong2 Aa = *(const ulonglong2*)(ap);      // rows rr0, rr0+1
                const ulonglong2 Ab = *(const ulonglong2*)(ap + 4);  // rows rr0+2, rr0+3
                const ulonglong2 w = *(const ulonglong2*)(Wl + (size_t)k * HH);
                ffma2(acc[0], w.x, Aa.x);  ffma2(acc[1], w.x, Aa.y);
                ffma2(acc[2], w.x, Ab.x);  ffma2(acc[3], w.x, Ab.y);
                ffma2(acc[4], w.y, Aa.x);  ffma2(acc[5], w.y, Aa.y);
                ffma2(acc[6], w.y, Ab.x);  ffma2(acc[7], w.y, Ab.y);
            }

            #pragma unroll
            for (int r = 0; r < 4; ++r) {
                float v0, v1, v2, v3;
                upk2(acc[0 + r], v0, v1);
                upk2(acc[4 + r], v2, v3);
                v0 += 0.0f; // (biases already folded)
                const int row = rr0 + r;
                const float s0 = v0 * sigf(v0);
                const float s1 = v1 * sigf(v1);
                const float s2 = v2 * sigf(v2);
                const float s3 = v3 * sigf(v3);
                *(ull*)(nA + (DIN + c0 + 0) * SASD + (row << 1)) = pk2(s0, s0);
                *(ull*)(nA + (DIN + c0 + 1) * SASD + (row << 1)) = pk2(s1, s1);
                *(ull*)(nA + (DIN + c0 + 2) * SASD + (row << 1)) = pk2(s2, s2);
                *(ull*)(nA + (DIN + c0 + 3) * SASD + (row << 1)) = pk2(s3, s3);
            }
            __syncthreads();
            float* tmp = cA; cA = nA; nA = tmp;
        }

        // ---- output layer: [32x256] @ [256x64] + bout; K split (cg2>>5)
        const int khalf = cg2 >> 5;
        const int c0    = (cg2 & 31) << 1;
        const float* Wo = Wout + c0;
        const int kb    = khalf << 7;

        ull acco[4];
        const ull binit = khalf ? 0ull : pk2(bout[c0], bout[c0 + 1]);
        #pragma unroll
        for (int i = 0; i < 4; ++i) acco[i] = binit;

        #pragma unroll 4
        for (int k = 0; k < 128; ++k) {
            const float* ap = cA + (DIN + kb + k) * SASD + (rr0 << 1);
            const ulonglong2 Aa = *(const ulonglong2*)(ap);
            const ulonglong2 Ab = *(const ulonglong2*)(ap + 4);
            const ull w = *(const ull*)(Wo + (size_t)(kb + k) * OUTD);
            ffma2(acco[0], w, Aa.x);
            ffma2(acco[1], w, Aa.y);
            ffma2(acco[2], w, Ab.x);
            ffma2(acco[3], w, Ab.y);
        }
        float* scr = nA;   // scratch (non-dup offsets, scratch only)
        if (khalf == 1) {
            #pragma unroll
            for (int r = 0; r < 4; ++r) {
                float v0, v1; upk2(acco[r], v0, v1);
                scr[(c0 + 0) * SASD + rr0 + r] = v0;
                scr[(c0 + 1) * SASD + rr0 + r] = v1;
            }
        }
        __syncthreads();
        if (khalf == 0) {
            #pragma unroll
            for (int r = 0; r < 4; ++r) {
                float v0, v1; upk2(acco[r], v0, v1);
                v0 += scr[(c0 + 0) * SASD + rr0 + r];
                v1 += scr[(c0 + 1) * SASD + rr0 + r];
                *(float2*)(out + (size_t)(row0 + rr0 + r) * OUTD + c0) =
                    make_float2(v0, v1);
            }
        }
    }
}

extern "C" void kernel_launch(void* const* d_in, const int* in_sizes, int n_in,
                              void* d_out, int out_size)
{
    const float* traj = (const float*)d_in[0];
    const float* act  = (const float*)d_in[1];
    const float* Wi   = (const float*)d_in[2];
    const float* Wh   = (const float*)d_in[3];
    const float* bh   = (const float*)d_in[4];
    const float* mlpW = (const float*)d_in[5];
    const float* mlpB = (const float*)d_in[6];
    const float* Wout = (const float*)d_in[7];
    const float* bout = (const float*)d_in[8];
    float* out = (float*)d_out;

    repack_kernel<<<(KTOT * G4 + 511) / 512, 512>>>(Wi, Wh);

    cudaFuncSetAttribute(lstm_fwd_kernel,
                         cudaFuncAttributeMaxDynamicSharedMemorySize,
                         SMEM_FLOATS * (int)sizeof(float));
    lstm_fwd_kernel<<<NCTA, NTH, SMEM_FLOATS * sizeof(float)>>>(
        traj, act, bh, mlpW, mlpB, Wout, bout, out);
}

// round 17
// speedup vs baseline: 1.8967x; 1.8967x over previous
#include <cuda_runtime.h>
#include <cstdint>

// Problem constants
#define BB   4096
#define TT   50
#define OBS  64
#define ACTD 16
#define DIN  80      // OBS + ACT
#define HH   256
#define G4   1024    // 4*H
#define NL   5
#define OUTD 64
#define KTOT 336

// Kernel config
#define RPB  32            // batch rows per CTA
#define NCTA (BB / RPB)    // 128
#define NTH  512
#define NW   16            // warps
#define SAS  36            // sA row stride in floats
#define PAN  14            // panel depth (336 = 24*14)
#define NPAN 24
#define PFLT (PAN * 64)    // 896 floats per warp panel
#define NBUF 2

// Shared memory (floats)
#define OFF_A0 0
#define OFF_A1 (KTOT * SAS)             // 12096
#define OFF_SB (2 * KTOT * SAS)         // 24192
#define OFF_P  (OFF_SB + G4)            // 25216
#define SMEM_FLOATS (OFF_P + NW * NBUF * PFLT)   // 53888 floats = 215552 B

typedef unsigned long long ull;

// Repacked LSTM weights: W6[k][wid<16][cgl<8][g<4][c<2]
__device__ float W6buf[KTOT * G4];

__device__ __forceinline__ float sigf(float x) {
    return __fdividef(1.0f, 1.0f + __expf(-x));
}
__device__ __forceinline__ void ffma2(ull &d, ull a, ull b) {
    asm("fma.rn.f32x2 %0, %1, %2, %0;" : "+l"(d) : "l"(a), "l"(b));
}
__device__ __forceinline__ ull pk2(float lo, float hi) {
    ull r; asm("mov.b64 %0, {%1, %2};" : "=l"(r) : "f"(lo), "f"(hi)); return r;
}
__device__ __forceinline__ void upk2(ull v, float &lo, float &hi) {
    asm("mov.b64 {%0, %1}, %2;" : "=f"(lo), "=f"(hi) : "l"(v));
}
__device__ __forceinline__ uint32_t smem_u32(const void* p) {
    uint32_t a;
    asm("{ .reg .u64 t; cvta.to.shared.u64 t, %1; cvt.u32.u64 %0, t; }"
        : "=r"(a) : "l"(p));
    return a;
}
__device__ __forceinline__ void cpa16(uint32_t s, const float* g) {
    asm volatile("cp.async.cg.shared.global [%0], [%1], 16;" :: "r"(s), "l"(g));
}
#define CP_COMMIT() asm volatile("cp.async.commit_group;" ::: "memory")
#define CP_WAIT(n)  asm volatile("cp.async.wait_group %0;" :: "n"(n) : "memory")

__device__ __forceinline__ float gatef(float zi, float zf, float zg, float zo,
                                       float &c)
{
    const float ig = sigf(zi);
    const float fg = sigf(zf);
    const float gg = zg * sigf(zg);       // silu
    const float og = sigf(zo);
    const float cn = fg * c + ig * gg;
    c = cn;
    return og * cn * sigf(cn);            // o * silu(c_new)
}

// ---------------- prepass: repack [Wi;Wh] into W6 layout ----------------
__global__ void repack_kernel(const float* __restrict__ Wi,
                              const float* __restrict__ Wh)
{
    const int i = blockIdx.x * blockDim.x + threadIdx.x;
    if (i >= KTOT * G4) return;
    const int k   = i >> 10;
    const int rem = i & 1023;
    const int wid = rem >> 6;          // 0..15
    const int r6  = rem & 63;
    const int cgl = r6 >> 3;           // 0..7
    const int g   = (r6 >> 1) & 3;
    const int c   = r6 & 1;
    const int col = (g << 8) + (((wid << 3) + cgl) << 1) + c;
    W6buf[i] = (k < DIN) ? Wi[(size_t)k * G4 + col]
                         : Wh[(size_t)(k - DIN) * G4 + col];
}

__global__ void __launch_bounds__(NTH, 1)
lstm_fwd_kernel(const float* __restrict__ traj, const float* __restrict__ act,
                const float* __restrict__ bh,   const float* __restrict__ mlpW,
                const float* __restrict__ mlpB, const float* __restrict__ Wout,
                const float* __restrict__ bout, float* __restrict__ out)
{
    extern __shared__ float sm[];
    float* sB = sm + OFF_SB;

    const int tid  = threadIdx.x;
    const int lane = tid & 31;
    const int wid  = tid >> 5;       // 0..15
    const int row0 = blockIdx.x * RPB;
    const int rgrp = tid & 3;        // 4 row groups x 8 rows
    const int cgrp = tid >> 2;       // 0..127 colpairs (all 256 hk)
    const int cgl  = cgrp & 7;       // colpair within warp
    const int r0   = rgrp << 3;      // 0, 8, 16, 24

    float* cA = sm + OFF_A0;
    float* nA = sm + OFF_A1;
    float* pwarp = sm + OFF_P + wid * (NBUF * PFLT);
    const uint32_t pwb = smem_u32(pwarp);
    const float* wsrc = W6buf + (wid << 6);     // + k*1024

    // per-lane prefetch offsets: 7 x 16B chunks per panel (896 floats/warp)
    uint32_t pdst[7];
    uint32_t psrc[7];
    #pragma unroll
    for (int j = 0; j < 7; ++j) {
        const int o  = lane + (j << 5);   // 0..223
        const int kk = o >> 4;            // 0..13 (k row within panel)
        const int ch = o & 15;            // 16B chunk within 64-float row
        pdst[j] = (uint32_t)(kk * 64 + ch * 4) * 4;
        psrc[j] = (uint32_t)(kk * G4 + ch * 4);
    }

    const int hk0 = cgrp << 1;       // thread's col pair

    // cell state: creg[c*8 + r]
    float creg[16];
    #pragma unroll
    for (int i = 0; i < 16; ++i) creg[i] = 0.0f;

    // init
    for (int i = tid; i < HH * SAS; i += NTH) cA[DIN * SAS + i] = 0.0f;
    for (int i = tid; i < G4; i += NTH) sB[i] = bh[i];
    for (int i = tid; i < DIN * RPB; i += NTH) {
        const int r = i & 31, k = i >> 5;
        const int row = row0 + r;
        float v;
        if (k < OBS) v = traj[((size_t)row * TT) * OBS + k];
        else         v = act [((size_t)row * TT) * ACTD + (k - OBS)];
        cA[k * SAS + r] = v;
    }
    __syncthreads();

    // hoisted per-t invariants ------------------------------------------
    ull bgate[4];
    #pragma unroll
    for (int g = 0; g < 4; ++g)
        bgate[g] = pk2(sB[(g << 8) + hk0], sB[(g << 8) + hk0 + 1]);

    const float* xptr[5];
    int xoff[5];
    #pragma unroll
    for (int it = 0; it < 5; ++it) {
        const int i = tid + it * NTH;
        const int r = i & 31, k = i >> 5;
        const int row = row0 + r;
        xoff[it] = k * SAS + r;
        if (it < 4) xptr[it] = traj + ((size_t)row * TT + 1) * OBS + k;
        else        xptr[it] = act  + ((size_t)row * TT + 1) * ACTD + (k - OBS);
    }

    // prime ring: panel 0 -> buf 0
    #pragma unroll
    for (int j = 0; j < 7; ++j) cpa16(pwb + pdst[j], wsrc + psrc[j]);
    CP_COMMIT();

    int cb = 0;         // consume buffer
    int fpan = 1;       // next panel to fetch (mod NPAN; stream periodic in t)

    // ============================ LSTM over time ============================
    for (int t = 0; t < TT; ++t) {
        // acc[g*8 + r], bias-initialized from hoisted packs
        ull acc[32];
        #pragma unroll
        for (int g = 0; g < 4; ++g) {
            #pragma unroll
            for (int r = 0; r < 8; ++r) acc[g * 8 + r] = bgate[g];
        }

        // prefetch x(t+1) into registers (pointers pre-advanced)
        float xv[5];
        if (t + 1 < TT) {
            #pragma unroll
            for (int it = 0; it < 5; ++it) xv[it] = *xptr[it];
            #pragma unroll
            for (int it = 0; it < 4; ++it) xptr[it] += OBS;
            xptr[4] += ACTD;
        }

        for (int p = 0; p < NPAN; ++p) {
            // prefetch next panel into the other buffer (periodic stream)
            {
                const float* s = wsrc + (size_t)fpan * (PAN * G4);
                const uint32_t d = pwb + (uint32_t)(cb ^ 1) * (PFLT * 4);
                #pragma unroll
                for (int j = 0; j < 7; ++j) cpa16(d + pdst[j], s + psrc[j]);
                CP_COMMIT();
                if (++fpan == NPAN) fpan = 0;
            }
            CP_WAIT(1);          // current panel (buf cb) complete
            __syncwarp();

            const float* panel = pwarp + cb * PFLT + (cgl << 3);
            const float* aptr  = cA + (p * PAN) * SAS + r0;
            #pragma unroll
            for (int kk = 0; kk < PAN; ++kk) {
                const float4 A0 = *(const float4*)(aptr);
                const float4 A1 = *(const float4*)(aptr + 4);
                const ull a0 = pk2(A0.x, A0.x), a1 = pk2(A0.y, A0.y);
                const ull a2 = pk2(A0.z, A0.z), a3 = pk2(A0.w, A0.w);
                const ull a4 = pk2(A1.x, A1.x), a5 = pk2(A1.y, A1.y);
                const ull a6 = pk2(A1.z, A1.z), a7 = pk2(A1.w, A1.w);
                const float* pr = panel + kk * 64;
                const ulonglong2 w01 = *(const ulonglong2*)(pr);     // g0, g1
                const ulonglong2 w23 = *(const ulonglong2*)(pr + 4); // g2, g3
                ffma2(acc[ 0], w01.x, a0); ffma2(acc[ 1], w01.x, a1);
                ffma2(acc[ 2], w01.x, a2); ffma2(acc[ 3], w01.x, a3);
                ffma2(acc[ 4], w01.x, a4); ffma2(acc[ 5], w01.x, a5);
                ffma2(acc[ 6], w01.x, a6); ffma2(acc[ 7], w01.x, a7);
                ffma2(acc[ 8], w01.y, a0); ffma2(acc[ 9], w01.y, a1);
                ffma2(acc[10], w01.y, a2); ffma2(acc[11], w01.y, a3);
                ffma2(acc[12], w01.y, a4); ffma2(acc[13], w01.y, a5);
                ffma2(acc[14], w01.y, a6); ffma2(acc[15], w01.y, a7);
                ffma2(acc[16], w23.x, a0); ffma2(acc[17], w23.x, a1);
                ffma2(acc[18], w23.x, a2); ffma2(acc[19], w23.x, a3);
                ffma2(acc[20], w23.x, a4); ffma2(acc[21], w23.x, a5);
                ffma2(acc[22], w23.x, a6); ffma2(acc[23], w23.x, a7);
                ffma2(acc[24], w23.y, a0); ffma2(acc[25], w23.y, a1);
                ffma2(acc[26], w23.y, a2); ffma2(acc[27], w23.y, a3);
                ffma2(acc[28], w23.y, a4); ffma2(acc[29], w23.y, a5);
                ffma2(acc[30], w23.y, a6); ffma2(acc[31], w23.y, a7);
                aptr += SAS;
            }
            __syncwarp();        // all lanes done before buf reuse
            cb ^= 1;
        }

        // gate epilogue -> h_new into NEXT buffer (8 rows x 2 cols)
        #pragma unroll
        for (int r = 0; r < 8; ++r) {
            float zi0, zi1, zf0, zf1, zg0, zg1, zo0, zo1;
            upk2(acc[ 0 + r], zi0, zi1);
            upk2(acc[ 8 + r], zf0, zf1);
            upk2(acc[16 + r], zg0, zg1);
            upk2(acc[24 + r], zo0, zo1);
            const float h0 = gatef(zi0, zf0, zg0, zo0, creg[r]);
            const float h1 = gatef(zi1, zf1, zg1, zo1, creg[8 + r]);
            const int row = r0 + r;
            nA[(DIN + hk0)     * SAS + row] = h0;
            nA[(DIN + hk0 + 1) * SAS + row] = h1;
        }

        // commit x(t+1) at hoisted offsets; single barrier; swap
        if (t + 1 < TT) {
            #pragma unroll
            for (int it = 0; it < 5; ++it) nA[xoff[it]] = xv[it];
        }
        __syncthreads();
        float* tmp = cA; cA = nA; nA = tmp;
    }
    CP_WAIT(0);   // drain overhanging prefetch

    // ============================ MLP head ============================
    // Thread: 4 rows x 4 cols per thread (unchanged champion tail)
    {
        const int rg2 = tid & 7;
        const int cg2 = tid >> 3;        // 0..63
        const int rr0 = rg2 << 2;

        for (int l = 0; l < NL; ++l) {
            const float* Wl = mlpW + (size_t)l * HH * HH + (cg2 << 2);
            const int c0 = cg2 << 2;

            ull acc[8];
            {
                const ull b01 = pk2(mlpB[l * HH + c0],     mlpB[l * HH + c0 + 1]);
                const ull b23 = pk2(mlpB[l * HH + c0 + 2], mlpB[l * HH + c0 + 3]);
                #pragma unroll
                for (int r = 0; r < 4; ++r) { acc[r] = b01; acc[4 + r] = b23; }
            }

            #pragma unroll 4
            for (int k = 0; k < HH; ++k) {
                const float4 a = *(const float4*)(cA + (DIN + k) * SAS + rr0);
                const ull a0 = pk2(a.x, a.x), a1 = pk2(a.y, a.y);
                const ull a2 = pk2(a.z, a.z), a3 = pk2(a.w, a.w);
                const ulonglong2 w = *(const ulonglong2*)(Wl + (size_t)k * HH);
                ffma2(acc[0], w.x, a0);  ffma2(acc[1], w.x, a1);
                ffma2(acc[2], w.x, a2);  ffma2(acc[3], w.x, a3);
                ffma2(acc[4], w.y, a0);  ffma2(acc[5], w.y, a1);
                ffma2(acc[6], w.y, a2);  ffma2(acc[7], w.y, a3);
            }

            #pragma unroll
            for (int r = 0; r < 4; ++r) {
                float v0, v1, v2, v3;
                upk2(acc[0 + r], v0, v1);
                upk2(acc[4 + r], v2, v3);
                const int row = rr0 + r;
                nA[(DIN + c0 + 0) * SAS + row] = v0 * sigf(v0);
                nA[(DIN + c0 + 1) * SAS + row] = v1 * sigf(v1);
                nA[(DIN + c0 + 2) * SAS + row] = v2 * sigf(v2);
                nA[(DIN + c0 + 3) * SAS + row] = v3 * sigf(v3);
            }
            __syncthreads();
            float* tmp = cA; cA = nA; nA = tmp;
        }

        // ---- output layer: [32x256] @ [256x64] + bout; K split (cg2>>5)
        const int khalf = cg2 >> 5;
        const int c0    = (cg2 & 31) << 1;
        const float* Wo = Wout + c0;
        const int kb    = khalf << 7;

        ull acco[4];
        const ull binit = khalf ? 0ull : pk2(bout[c0], bout[c0 + 1]);
        #pragma unroll
        for (int i = 0; i < 4; ++i) acco[i] = binit;

        #pragma unroll 4
        for (int k = 0; k < 128; ++k) {
            const float4 a = *(const float4*)(cA + (DIN + kb + k) * SAS + rr0);
            const ull w = *(const ull*)(Wo + (size_t)(kb + k) * OUTD);
            ffma2(acco[0], w, pk2(a.x, a.x));
            ffma2(acco[1], w, pk2(a.y, a.y));
            ffma2(acco[2], w, pk2(a.z, a.z));
            ffma2(acco[3], w, pk2(a.w, a.w));
        }
        float* scr = nA;
        if (khalf == 1) {
            #pragma unroll
            for (int r = 0; r < 4; ++r) {
                float v0, v1; upk2(acco[r], v0, v1);
                scr[(c0 + 0) * SAS + rr0 + r] = v0;
                scr[(c0 + 1) * SAS + rr0 + r] = v1;
            }
        }
        __syncthreads();
        if (khalf == 0) {
            #pragma unroll
            for (int r = 0; r < 4; ++r) {
                float v0, v1; upk2(acco[r], v0, v1);
                v0 += scr[(c0 + 0) * SAS + rr0 + r];
                v1 += scr[(c0 + 1) * SAS + rr0 + r];
                *(float2*)(out + (size_t)(row0 + rr0 + r) * OUTD + c0) =
                    make_float2(v0, v1);
            }
        }
    }
}

extern "C" void kernel_launch(void* const* d_in, const int* in_sizes, int n_in,
                              void* d_out, int out_size)
{
    const float* traj = (const float*)d_in[0];
    const float* act  = (const float*)d_in[1];
    const float* Wi   = (const float*)d_in[2];
    const float* Wh   = (const float*)d_in[3];
    const float* bh   = (const float*)d_in[4];
    const float* mlpW = (const float*)d_in[5];
    const float* mlpB = (const float*)d_in[6];
    const float* Wout = (const float*)d_in[7];
    const float* bout = (const float*)d_in[8];
    float* out = (float*)d_out;

    repack_kernel<<<(KTOT * G4 + 511) / 512, 512>>>(Wi, Wh);

    cudaFuncSetAttribute(lstm_fwd_kernel,
                         cudaFuncAttributeMaxDynamicSharedMemorySize,
                         SMEM_FLOATS * (int)sizeof(float));
    lstm_fwd_kernel<<<NCTA, NTH, SMEM_FLOATS * sizeof(float)>>>(
        traj, act, bh, mlpW, mlpB, Wout, bout, out);
}